// round 2
// baseline (speedup 1.0000x reference)
#include <cuda_runtime.h>

#define NFEAT 8192
#define PDIM 256
#define RDIM 512
#define MROWS 32
#define AATOMS 64
#define NROWS 2048   // M*A
#define NSTACKS 32
#define NS 4

#define BM 64
#define BN 64
#define BK 32

// scratch (static device globals; no allocation in kernel_launch)
__device__ float g_proj[NROWS * PDIM];     // projection per (m,a), only for its own charge
__device__ int   g_cnt[NS];
__device__ int   g_list[NS * NROWS];
__device__ float g_partial[NROWS];

__global__ void k_init() {
    if (threadIdx.x < NS) g_cnt[threadIdx.x] = 0;
}

__global__ void k_classify(const int* __restrict__ charges) {
    int row = blockIdx.x * blockDim.x + threadIdx.x;
    if (row < NROWS) {
        int s = charges[row];
        int pos = atomicAdd(&g_cnt[s], 1);
        g_list[s * NROWS + pos] = row;
    }
}

// Charge-grouped GEMM: proj[row, :] = rep[row, :] @ reductors[charge(row)]
// grid: (P/BN=4, NROWS/BM=32 worst case, NS=4), block: 256 (16x16), 4x4 microtile
__global__ void k_gemm(const float* __restrict__ rep,
                       const float* __restrict__ reductors) {
    int s = blockIdx.z;
    int cnt = g_cnt[s];
    int row0 = blockIdx.y * BM;
    if (row0 >= cnt) return;

    __shared__ int   rowIdx[BM];
    __shared__ float As[BK][BM];
    __shared__ float Bs[BK][BN];

    int t  = threadIdx.x;
    int tx = t & 15;
    int ty = t >> 4;

    if (t < BM) {
        int gi = row0 + t;
        rowIdx[t] = (gi < cnt) ? g_list[s * NROWS + gi] : -1;
    }
    __syncthreads();

    float acc[4][4] = {};
    const float* redS = reductors + s * RDIM * PDIM + blockIdx.x * BN;

    for (int kb = 0; kb < RDIM; kb += BK) {
        // load A tile (gathered rows), 512 float4 slots, 2 per thread
        #pragma unroll
        for (int i = 0; i < 2; i++) {
            int slot = t * 2 + i;
            int r  = slot >> 3;   // tile row 0..63
            int kq = slot & 7;    // which float4 in the BK=32 chunk
            int grow = rowIdx[r];
            float4 v = make_float4(0.f, 0.f, 0.f, 0.f);
            if (grow >= 0)
                v = *(const float4*)(rep + grow * RDIM + kb + kq * 4);
            As[kq * 4 + 0][r] = v.x;
            As[kq * 4 + 1][r] = v.y;
            As[kq * 4 + 2][r] = v.z;
            As[kq * 4 + 3][r] = v.w;
        }
        // load B tile: slot -> k = slot/16, col-quad = slot%16 (coalesced)
        #pragma unroll
        for (int i = 0; i < 2; i++) {
            int slot = t * 2 + i;
            int k  = slot >> 4;
            int cq = slot & 15;
            float4 v = *(const float4*)(redS + (kb + k) * PDIM + cq * 4);
            *(float4*)&Bs[k][cq * 4] = v;
        }
        __syncthreads();

        #pragma unroll
        for (int k = 0; k < BK; k++) {
            float4 a4 = *(const float4*)&As[k][ty * 4];
            float4 b4 = *(const float4*)&Bs[k][tx * 4];
            float av[4] = {a4.x, a4.y, a4.z, a4.w};
            float bv[4] = {b4.x, b4.y, b4.z, b4.w};
            #pragma unroll
            for (int ii = 0; ii < 4; ii++)
                #pragma unroll
                for (int jj = 0; jj < 4; jj++)
                    acc[ii][jj] += av[ii] * bv[jj];
        }
        __syncthreads();
    }

    #pragma unroll
    for (int ii = 0; ii < 4; ii++) {
        int r = rowIdx[ty * 4 + ii];
        if (r >= 0) {
            float4 v = make_float4(acc[ii][0], acc[ii][1], acc[ii][2], acc[ii][3]);
            *(float4*)(g_proj + r * PDIM + blockIdx.x * BN + tx * 4) = v;
        }
    }
}

// One warp per (m,a): keep 256 proj values as 8 regs/lane; for each of 32
// stacks: apply D signs, FWHT-256 (3 in-register stages + 5 shfl stages),
// cos(x+bias)*alpha, accumulate. Element index i = lane*8 + j.
__global__ void k_feat(const int* __restrict__ charges,
                       const float* __restrict__ Dmat,
                       const float* __restrict__ bias,
                       const float* __restrict__ alpha) {
    int warpId = threadIdx.x >> 5;
    int lane   = threadIdx.x & 31;
    int pair   = blockIdx.x * (blockDim.x >> 5) + warpId;   // 0..2047

    int s = charges[pair];
    const float* pp = g_proj + pair * PDIM + lane * 8;
    float4 p0 = *(const float4*)pp;
    float4 p1 = *(const float4*)(pp + 4);
    // fold in the FWHT normalization d^{-1/2} = 1/16 (COEFF_NORM == 1 exactly)
    float proj[8] = {p0.x * 0.0625f, p0.y * 0.0625f, p0.z * 0.0625f, p0.w * 0.0625f,
                     p1.x * 0.0625f, p1.y * 0.0625f, p1.z * 0.0625f, p1.w * 0.0625f};

    const float* Ds = Dmat + s * NSTACKS * PDIM;
    const float* bs = bias + s * NFEAT;

    float sum = 0.f;
    for (int st = 0; st < NSTACKS; st++) {
        const float* dp = Ds + st * PDIM + lane * 8;
        float4 d0 = *(const float4*)dp;
        float4 d1 = *(const float4*)(dp + 4);
        float dv[8] = {d0.x, d0.y, d0.z, d0.w, d1.x, d1.y, d1.z, d1.w};
        float v[8];
        #pragma unroll
        for (int j = 0; j < 8; j++)
            v[j] = (dv[j] >= 0.f) ? proj[j] : -proj[j];

        // in-register butterflies: h = 1, 2, 4
        float tv;
        tv = v[0]; v[0] = tv + v[1]; v[1] = tv - v[1];
        tv = v[2]; v[2] = tv + v[3]; v[3] = tv - v[3];
        tv = v[4]; v[4] = tv + v[5]; v[5] = tv - v[5];
        tv = v[6]; v[6] = tv + v[7]; v[7] = tv - v[7];

        tv = v[0]; v[0] = tv + v[2]; v[2] = tv - v[2];
        tv = v[1]; v[1] = tv + v[3]; v[3] = tv - v[3];
        tv = v[4]; v[4] = tv + v[6]; v[6] = tv - v[6];
        tv = v[5]; v[5] = tv + v[7]; v[7] = tv - v[7];

        tv = v[0]; v[0] = tv + v[4]; v[4] = tv - v[4];
        tv = v[1]; v[1] = tv + v[5]; v[5] = tv - v[5];
        tv = v[2]; v[2] = tv + v[6]; v[6] = tv - v[6];
        tv = v[3]; v[3] = tv + v[7]; v[7] = tv - v[7];

        // cross-lane butterflies: h = 8,16,32,64,128  ->  lane masks 1,2,4,8,16
        #pragma unroll
        for (int msk = 1; msk <= 16; msk <<= 1) {
            #pragma unroll
            for (int j = 0; j < 8; j++) {
                float o = __shfl_xor_sync(0xffffffffu, v[j], msk);
                v[j] = (lane & msk) ? (o - v[j]) : (v[j] + o);
            }
        }

        const float* bp = bs + st * PDIM + lane * 8;
        const float* ap = alpha + st * PDIM + lane * 8;
        float4 b0 = *(const float4*)bp;
        float4 b1 = *(const float4*)(bp + 4);
        float4 a0 = *(const float4*)ap;
        float4 a1 = *(const float4*)(ap + 4);
        float bb[8] = {b0.x, b0.y, b0.z, b0.w, b1.x, b1.y, b1.z, b1.w};
        float aa[8] = {a0.x, a0.y, a0.z, a0.w, a1.x, a1.y, a1.z, a1.w};
        #pragma unroll
        for (int j = 0; j < 8; j++)
            sum += __cosf(v[j] + bb[j]) * aa[j];
    }

    #pragma unroll
    for (int off = 16; off; off >>= 1)
        sum += __shfl_down_sync(0xffffffffu, sum, off);
    if (lane == 0) g_partial[pair] = sum;
}

// deterministic final reduction over atoms: out[m] = FEAT_NORM * sum_a partial
__global__ void k_reduce(float* __restrict__ out) {
    int m = blockIdx.x;
    int t = threadIdx.x;   // 64 threads
    float v = g_partial[m * AATOMS + t];
    #pragma unroll
    for (int off = 16; off; off >>= 1)
        v += __shfl_down_sync(0xffffffffu, v, off);
    __shared__ float sm2[2];
    if ((t & 31) == 0) sm2[t >> 5] = v;
    __syncthreads();
    if (t == 0) out[m] = 0.015625f * (sm2[0] + sm2[1]);   // FEAT_NORM = 1/64
}

extern "C" void kernel_launch(void* const* d_in, const int* in_sizes, int n_in,
                              void* d_out, int out_size) {
    const float* rep       = (const float*)d_in[0];
    const int*   charges   = (const int*)d_in[1];
    const float* reductors = (const float*)d_in[2];
    const float* Dmat      = (const float*)d_in[3];
    const float* bias      = (const float*)d_in[4];
    const float* alpha     = (const float*)d_in[5];
    float* out = (float*)d_out;

    k_init<<<1, 32>>>();
    k_classify<<<8, 256>>>(charges);
    dim3 gg(PDIM / BN, NROWS / BM, NS);   // (4, 32, 4); empty row-blocks exit early
    k_gemm<<<gg, 256>>>(rep, reductors);
    k_feat<<<NROWS / 8, 256>>>(charges, Dmat, bias, alpha);
    k_reduce<<<MROWS, AATOMS>>>(out);
}

// round 4
// speedup vs baseline: 2.1185x; 2.1185x over previous
#include <cuda_runtime.h>

#define NFEAT 8192
#define PDIM 256
#define RDIM 512
#define MROWS 32
#define AATOMS 64
#define NROWS 2048   // M*A
#define NSTACKS 32
#define NS 4
#define KSPLIT 4
#define KCHUNK (RDIM / KSPLIT)   // 128

#define BM 64
#define BN 64
#define BK 32

typedef unsigned long long ull;

// scratch (static device globals; no allocation in kernel_launch)
__device__ float g_proj4[KSPLIT * NROWS * PDIM];   // split-K partial projections
__device__ int   g_cnt[NS];
__device__ int   g_list[NS * NROWS];
__device__ float g_partial[NROWS * 4];             // 4 stack-groups per (m,a)

__device__ __forceinline__ ull pack2(float lo, float hi) {
    ull d;
    asm("mov.b64 %0, {%1, %2};" : "=l"(d) : "r"(__float_as_uint(lo)), "r"(__float_as_uint(hi)));
    return d;
}
__device__ __forceinline__ ull fma2(ull a, ull b, ull c) {
    ull d;
    asm("fma.rn.f32x2 %0, %1, %2, %3;" : "=l"(d) : "l"(a), "l"(b), "l"(c));
    return d;
}
__device__ __forceinline__ void unpack2(ull v, float& lo, float& hi) {
    unsigned int l, h;
    asm("mov.b64 {%0, %1}, %2;" : "=r"(l), "=r"(h) : "l"(v));
    lo = __uint_as_float(l); hi = __uint_as_float(h);
}

__global__ void k_init() {
    if (threadIdx.x < NS) g_cnt[threadIdx.x] = 0;
}

__global__ void k_classify(const int* __restrict__ charges) {
    int row = blockIdx.x * blockDim.x + threadIdx.x;
    if (row < NROWS) {
        int s = charges[row];
        int pos = atomicAdd(&g_cnt[s], 1);
        g_list[s * NROWS + pos] = row;
    }
}

// Charge-grouped split-K GEMM:
// g_proj4[kslice][row, :] += rep[row, k0:k0+128] @ reductors[charge(row)][k0:k0+128, :]
// grid: (4 N-tiles * 4 k-slices, 32 row-blocks, 4 charges), block 256 (16x16), 4x4 microtile
__global__ void k_gemm(const float* __restrict__ rep,
                       const float* __restrict__ reductors) {
    int s = blockIdx.z;
    int cnt = g_cnt[s];
    int row0 = blockIdx.y * BM;
    if (row0 >= cnt) return;

    int ntile  = blockIdx.x & 3;
    int kslice = blockIdx.x >> 2;
    int k0 = kslice * KCHUNK;

    __shared__ int   rowIdx[BM];
    __shared__ float As[BK][BM];
    __shared__ float Bs[BK][BN];

    int t  = threadIdx.x;
    int tx = t & 15;
    int ty = t >> 4;

    if (t < BM) {
        int gi = row0 + t;
        rowIdx[t] = (gi < cnt) ? g_list[s * NROWS + gi] : -1;
    }
    __syncthreads();

    // packed accumulators: acc2[jj][h] = (acc[2h][jj], acc[2h+1][jj])
    ull acc2[4][2] = {};
    const float* redS = reductors + s * RDIM * PDIM + ntile * BN;

    for (int kb = k0; kb < k0 + KCHUNK; kb += BK) {
        #pragma unroll
        for (int i = 0; i < 2; i++) {
            int slot = t * 2 + i;
            int r  = slot >> 3;
            int kq = slot & 7;
            int grow = rowIdx[r];
            float4 v = make_float4(0.f, 0.f, 0.f, 0.f);
            if (grow >= 0)
                v = *(const float4*)(rep + grow * RDIM + kb + kq * 4);
            As[kq * 4 + 0][r] = v.x;
            As[kq * 4 + 1][r] = v.y;
            As[kq * 4 + 2][r] = v.z;
            As[kq * 4 + 3][r] = v.w;
        }
        #pragma unroll
        for (int i = 0; i < 2; i++) {
            int slot = t * 2 + i;
            int k  = slot >> 4;
            int cq = slot & 15;
            float4 v = *(const float4*)(redS + (kb + k) * PDIM + cq * 4);
            *(float4*)&Bs[k][cq * 4] = v;
        }
        __syncthreads();

        #pragma unroll
        for (int k = 0; k < BK; k++) {
            float4 a4 = *(const float4*)&As[k][ty * 4];
            float4 b4 = *(const float4*)&Bs[k][tx * 4];
            ull a01 = pack2(a4.x, a4.y);
            ull a23 = pack2(a4.z, a4.w);
            float bv[4] = {b4.x, b4.y, b4.z, b4.w};
            #pragma unroll
            for (int jj = 0; jj < 4; jj++) {
                ull bd = pack2(bv[jj], bv[jj]);
                acc2[jj][0] = fma2(a01, bd, acc2[jj][0]);
                acc2[jj][1] = fma2(a23, bd, acc2[jj][1]);
            }
        }
        __syncthreads();
    }

    float acc[4][4];
    #pragma unroll
    for (int jj = 0; jj < 4; jj++) {
        unpack2(acc2[jj][0], acc[0][jj], acc[1][jj]);
        unpack2(acc2[jj][1], acc[2][jj], acc[3][jj]);
    }

    float* outSlice = g_proj4 + kslice * (NROWS * PDIM);
    #pragma unroll
    for (int ii = 0; ii < 4; ii++) {
        int r = rowIdx[ty * 4 + ii];
        if (r >= 0) {
            float4 v = make_float4(acc[ii][0], acc[ii][1], acc[ii][2], acc[ii][3]);
            *(float4*)(outSlice + r * PDIM + ntile * BN + tx * 4) = v;
        }
    }
}

// One warp per (pair, stack-group): 8192 tasks. Each warp sums the 4 split-K
// projection slices, then for 8 stacks: D signs, FWHT-256 (3 reg stages +
// 5 shfl stages), cos(x+bias)*alpha, accumulate.
__global__ void k_feat(const int* __restrict__ charges,
                       const float* __restrict__ Dmat,
                       const float* __restrict__ bias,
                       const float* __restrict__ alpha) {
    int warpId = threadIdx.x >> 5;
    int lane   = threadIdx.x & 31;
    int task   = blockIdx.x * (blockDim.x >> 5) + warpId;   // 0..8191
    int pair   = task >> 2;
    int grp    = task & 3;
    int st0    = grp * 8;

    int s = charges[pair];

    float proj[8];
    {
        const float* pp = g_proj4 + pair * PDIM + lane * 8;
        float4 p0 = *(const float4*)pp;
        float4 p1 = *(const float4*)(pp + 4);
        float acc[8] = {p0.x, p0.y, p0.z, p0.w, p1.x, p1.y, p1.z, p1.w};
        #pragma unroll
        for (int c = 1; c < KSPLIT; c++) {
            const float* pc = g_proj4 + c * (NROWS * PDIM) + pair * PDIM + lane * 8;
            float4 q0 = *(const float4*)pc;
            float4 q1 = *(const float4*)(pc + 4);
            acc[0] += q0.x; acc[1] += q0.y; acc[2] += q0.z; acc[3] += q0.w;
            acc[4] += q1.x; acc[5] += q1.y; acc[6] += q1.z; acc[7] += q1.w;
        }
        // fold FWHT normalization 1/16 (COEFF_NORM == 1 exactly)
        #pragma unroll
        for (int j = 0; j < 8; j++) proj[j] = acc[j] * 0.0625f;
    }

    const float* Ds = Dmat + s * NSTACKS * PDIM;
    const float* bs = bias + s * NFEAT;

    float sum = 0.f;
    for (int st = st0; st < st0 + 8; st++) {
        const float* dp = Ds + st * PDIM + lane * 8;
        float4 d0 = *(const float4*)dp;
        float4 d1 = *(const float4*)(dp + 4);
        float dv[8] = {d0.x, d0.y, d0.z, d0.w, d1.x, d1.y, d1.z, d1.w};
        float v[8];
        #pragma unroll
        for (int j = 0; j < 8; j++)
            v[j] = (dv[j] >= 0.f) ? proj[j] : -proj[j];

        float tv;
        tv = v[0]; v[0] = tv + v[1]; v[1] = tv - v[1];
        tv = v[2]; v[2] = tv + v[3]; v[3] = tv - v[3];
        tv = v[4]; v[4] = tv + v[5]; v[5] = tv - v[5];
        tv = v[6]; v[6] = tv + v[7]; v[7] = tv - v[7];

        tv = v[0]; v[0] = tv + v[2]; v[2] = tv - v[2];
        tv = v[1]; v[1] = tv + v[3]; v[3] = tv - v[3];
        tv = v[4]; v[4] = tv + v[6]; v[6] = tv - v[6];
        tv = v[5]; v[5] = tv + v[7]; v[7] = tv - v[7];

        tv = v[0]; v[0] = tv + v[4]; v[4] = tv - v[4];
        tv = v[1]; v[1] = tv + v[5]; v[5] = tv - v[5];
        tv = v[2]; v[2] = tv + v[6]; v[6] = tv - v[6];
        tv = v[3]; v[3] = tv + v[7]; v[7] = tv - v[7];

        #pragma unroll
        for (int msk = 1; msk <= 16; msk <<= 1) {
            #pragma unroll
            for (int j = 0; j < 8; j++) {
                float o = __shfl_xor_sync(0xffffffffu, v[j], msk);
                v[j] = (lane & msk) ? (o - v[j]) : (v[j] + o);
            }
        }

        const float* bp = bs + st * PDIM + lane * 8;
        const float* ap = alpha + st * PDIM + lane * 8;
        float4 b0 = *(const float4*)bp;
        float4 b1 = *(const float4*)(bp + 4);
        float4 a0 = *(const float4*)ap;
        float4 a1 = *(const float4*)(ap + 4);
        float bb[8] = {b0.x, b0.y, b0.z, b0.w, b1.x, b1.y, b1.z, b1.w};
        float aa[8] = {a0.x, a0.y, a0.z, a0.w, a1.x, a1.y, a1.z, a1.w};
        #pragma unroll
        for (int j = 0; j < 8; j++)
            sum += __cosf(v[j] + bb[j]) * aa[j];
    }

    #pragma unroll
    for (int off = 16; off; off >>= 1)
        sum += __shfl_down_sync(0xffffffffu, sum, off);
    // task = pair*4+grp = m*256 + a*4 + grp -> contiguous 256 per m
    if (lane == 0) g_partial[task] = sum;
}

// out[m] = FEAT_NORM * sum over 256 contiguous partials
__global__ void k_reduce(float* __restrict__ out) {
    int m = blockIdx.x;
    int t = threadIdx.x;   // 256 threads
    float v = g_partial[m * 256 + t];
    #pragma unroll
    for (int off = 16; off; off >>= 1)
        v += __shfl_down_sync(0xffffffffu, v, off);
    __shared__ float sm8[8];
    if ((t & 31) == 0) sm8[t >> 5] = v;
    __syncthreads();
    if (t < 8) {
        float w = sm8[t];
        #pragma unroll
        for (int off = 4; off; off >>= 1)
            w += __shfl_down_sync(0xffu, w, off);
        if (t == 0) out[m] = 0.015625f * w;   // FEAT_NORM = 1/64
    }
}

extern "C" void kernel_launch(void* const* d_in, const int* in_sizes, int n_in,
                              void* d_out, int out_size) {
    const float* rep       = (const float*)d_in[0];
    const int*   charges   = (const int*)d_in[1];
    const float* reductors = (const float*)d_in[2];
    const float* Dmat      = (const float*)d_in[3];
    const float* bias      = (const float*)d_in[4];
    const float* alpha     = (const float*)d_in[5];
    float* out = (float*)d_out;

    k_init<<<1, 32>>>();
    k_classify<<<8, 256>>>(charges);
    dim3 gg(4 * KSPLIT, NROWS / BM, NS);   // (16, 32, 4); empty row-blocks exit early
    k_gemm<<<gg, 256>>>(rep, reductors);
    k_feat<<<NROWS * 4 / 8, 256>>>(charges, Dmat, bias, alpha);   // 1024 blocks, 8 warps each
    k_reduce<<<MROWS, 256>>>(out);
}

// round 5
// speedup vs baseline: 2.4320x; 1.1480x over previous
#include <cuda_runtime.h>

#define NFEAT 8192
#define PDIM 256
#define RDIM 512
#define MROWS 32
#define AATOMS 64
#define NROWS 2048   // M*A
#define NSTACKS 32
#define NS 4
#define KSPLIT 4
#define KCHUNK (RDIM / KSPLIT)   // 128

#define BM 64
#define BN 64
#define BK 32

typedef unsigned long long ull;
typedef unsigned int uint;

// scratch (static device globals; no allocation in kernel_launch)
__device__ float g_proj4[KSPLIT * NROWS * PDIM];   // split-K partial projections
__device__ int   g_cnt[NS];
__device__ int   g_list[NS * NROWS];
__device__ float g_partial[NROWS * 4];             // 4 stack-groups per (m,a)

__device__ __forceinline__ ull pack2(float lo, float hi) {
    ull d;
    asm("mov.b64 %0, {%1, %2};" : "=l"(d) : "r"(__float_as_uint(lo)), "r"(__float_as_uint(hi)));
    return d;
}
__device__ __forceinline__ ull fma2(ull a, ull b, ull c) {
    ull d;
    asm("fma.rn.f32x2 %0, %1, %2, %3;" : "=l"(d) : "l"(a), "l"(b), "l"(c));
    return d;
}
__device__ __forceinline__ void unpack2(ull v, float& lo, float& hi) {
    unsigned int l, h;
    asm("mov.b64 {%0, %1}, %2;" : "=r"(l), "=r"(h) : "l"(v));
    lo = __uint_as_float(l); hi = __uint_as_float(h);
}

// fused init + classify: one block, smem counters. List ORDER is atomic-order
// dependent but every row's GEMM result and output location are order-invariant,
// so final output bits are deterministic.
__global__ void k_classify(const int* __restrict__ charges) {
    __shared__ int scnt[NS];
    int t = threadIdx.x;
    if (t < NS) scnt[t] = 0;
    __syncthreads();
    for (int row = t; row < NROWS; row += 1024) {
        int s = charges[row];
        int pos = atomicAdd(&scnt[s], 1);
        g_list[s * NROWS + pos] = row;
    }
    __syncthreads();
    if (t < NS) g_cnt[t] = scnt[t];
}

// Charge-grouped split-K GEMM:
// g_proj4[kslice][row, :] = rep[row, k0:k0+128] @ reductors[charge(row)][k0:k0+128, :]
__global__ void k_gemm(const float* __restrict__ rep,
                       const float* __restrict__ reductors) {
    int s = blockIdx.z;
    int cnt = g_cnt[s];
    int row0 = blockIdx.y * BM;
    if (row0 >= cnt) return;

    int ntile  = blockIdx.x & 3;
    int kslice = blockIdx.x >> 2;
    int k0 = kslice * KCHUNK;

    __shared__ int   rowIdx[BM];
    __shared__ float As[BK][BM];
    __shared__ float Bs[BK][BN];

    int t  = threadIdx.x;
    int tx = t & 15;
    int ty = t >> 4;

    if (t < BM) {
        int gi = row0 + t;
        rowIdx[t] = (gi < cnt) ? g_list[s * NROWS + gi] : -1;
    }
    __syncthreads();

    ull acc2[4][2] = {};
    const float* redS = reductors + s * RDIM * PDIM + ntile * BN;

    for (int kb = k0; kb < k0 + KCHUNK; kb += BK) {
        #pragma unroll
        for (int i = 0; i < 2; i++) {
            int slot = t * 2 + i;
            int r  = slot >> 3;
            int kq = slot & 7;
            int grow = rowIdx[r];
            float4 v = make_float4(0.f, 0.f, 0.f, 0.f);
            if (grow >= 0)
                v = *(const float4*)(rep + grow * RDIM + kb + kq * 4);
            As[kq * 4 + 0][r] = v.x;
            As[kq * 4 + 1][r] = v.y;
            As[kq * 4 + 2][r] = v.z;
            As[kq * 4 + 3][r] = v.w;
        }
        #pragma unroll
        for (int i = 0; i < 2; i++) {
            int slot = t * 2 + i;
            int k  = slot >> 4;
            int cq = slot & 15;
            float4 v = *(const float4*)(redS + (kb + k) * PDIM + cq * 4);
            *(float4*)&Bs[k][cq * 4] = v;
        }
        __syncthreads();

        #pragma unroll
        for (int k = 0; k < BK; k++) {
            float4 a4 = *(const float4*)&As[k][ty * 4];
            float4 b4 = *(const float4*)&Bs[k][tx * 4];
            ull a01 = pack2(a4.x, a4.y);
            ull a23 = pack2(a4.z, a4.w);
            float bv[4] = {b4.x, b4.y, b4.z, b4.w};
            #pragma unroll
            for (int jj = 0; jj < 4; jj++) {
                ull bd = pack2(bv[jj], bv[jj]);
                acc2[jj][0] = fma2(a01, bd, acc2[jj][0]);
                acc2[jj][1] = fma2(a23, bd, acc2[jj][1]);
            }
        }
        __syncthreads();
    }

    float acc[4][4];
    #pragma unroll
    for (int jj = 0; jj < 4; jj++) {
        unpack2(acc2[jj][0], acc[0][jj], acc[1][jj]);
        unpack2(acc2[jj][1], acc[2][jj], acc[3][jj]);
    }

    float* outSlice = g_proj4 + kslice * (NROWS * PDIM);
    #pragma unroll
    for (int ii = 0; ii < 4; ii++) {
        int r = rowIdx[ty * 4 + ii];
        if (r >= 0) {
            float4 v = make_float4(acc[ii][0], acc[ii][1], acc[ii][2], acc[ii][3]);
            *(float4*)(outSlice + r * PDIM + ntile * BN + tx * 4) = v;
        }
    }
}

// One warp per (pair, stack-group). FWHT-256 with HALF-EXCHANGE lane stages:
// each of the 5 cross-lane stages shfls only 4 registers (not 8); the result
// layout is permuted such that element (lane q, reg r) holds logical feature
// index  i = 128*(r>>2) + (q>>1)*8 + (q&1)*4 + (r&3)  within the stack.
// For fixed q, regs 0..3 and 4..7 are contiguous runs -> bias/alpha still
// load as two float4s at bases b and b+128. Final alpha-dot is permutation
// invariant, so no correction needed.
__global__ void k_feat(const int* __restrict__ charges,
                       const float* __restrict__ Dmat,
                       const float* __restrict__ bias,
                       const float* __restrict__ alpha) {
    int warpId = threadIdx.x >> 5;
    int lane   = threadIdx.x & 31;
    int task   = blockIdx.x * (blockDim.x >> 5) + warpId;   // 0..8191
    int pair   = task >> 2;
    int grp    = task & 3;
    int st0    = grp * 8;

    int s = charges[pair];

    uint projb[8];
    {
        const float* pp = g_proj4 + pair * PDIM + lane * 8;
        float4 p0 = *(const float4*)pp;
        float4 p1 = *(const float4*)(pp + 4);
        float acc[8] = {p0.x, p0.y, p0.z, p0.w, p1.x, p1.y, p1.z, p1.w};
        #pragma unroll
        for (int c = 1; c < KSPLIT; c++) {
            const float* pc = g_proj4 + c * (NROWS * PDIM) + pair * PDIM + lane * 8;
            float4 q0 = *(const float4*)pc;
            float4 q1 = *(const float4*)(pc + 4);
            acc[0] += q0.x; acc[1] += q0.y; acc[2] += q0.z; acc[3] += q0.w;
            acc[4] += q1.x; acc[5] += q1.y; acc[6] += q1.z; acc[7] += q1.w;
        }
        // fold FWHT normalization 1/16 (COEFF_NORM == 1 exactly)
        #pragma unroll
        for (int j = 0; j < 8; j++) projb[j] = __float_as_uint(acc[j] * 0.0625f);
    }

    const float* Ds = Dmat + s * NSTACKS * PDIM;
    const float* bs = bias + s * NFEAT;

    // permuted bias/alpha base for this lane
    int pbase = ((lane >> 1) << 3) + ((lane & 1) << 2);

    float sum = 0.f;
    for (int st = st0; st < st0 + 8; st++) {
        // D sign application via sign-bit XOR
        const uint4* dp = (const uint4*)(Ds + st * PDIM + lane * 8);
        uint4 d0 = dp[0];
        uint4 d1 = dp[1];
        uint db[8] = {d0.x, d0.y, d0.z, d0.w, d1.x, d1.y, d1.z, d1.w};
        float v[8];
        #pragma unroll
        for (int j = 0; j < 8; j++)
            v[j] = __uint_as_float(projb[j] ^ (db[j] & 0x80000000u));

        // in-register butterflies: j bits 0,1,2
        float tv;
        tv = v[0]; v[0] = tv + v[1]; v[1] = tv - v[1];
        tv = v[2]; v[2] = tv + v[3]; v[3] = tv - v[3];
        tv = v[4]; v[4] = tv + v[5]; v[5] = tv - v[5];
        tv = v[6]; v[6] = tv + v[7]; v[7] = tv - v[7];

        tv = v[0]; v[0] = tv + v[2]; v[2] = tv - v[2];
        tv = v[1]; v[1] = tv + v[3]; v[3] = tv - v[3];
        tv = v[4]; v[4] = tv + v[6]; v[6] = tv - v[6];
        tv = v[5]; v[5] = tv + v[7]; v[7] = tv - v[7];

        tv = v[0]; v[0] = tv + v[4]; v[4] = tv - v[4];
        tv = v[1]; v[1] = tv + v[5]; v[5] = tv - v[5];
        tv = v[2]; v[2] = tv + v[6]; v[6] = tv - v[6];
        tv = v[3]; v[3] = tv + v[7]; v[7] = tv - v[7];

        // half-exchange cross-lane butterflies: masks 1,2,4,8,16
        #pragma unroll
        for (int msk = 1; msk <= 16; msk <<= 1) {
            bool hi = (lane & msk) != 0;
            float sgn = hi ? -1.f : 1.f;
            float nv[8];
            #pragma unroll
            for (int r = 0; r < 4; r++) {
                float send = hi ? v[r]     : v[r + 4];
                float keep = hi ? v[r + 4] : v[r];
                float recv = __shfl_xor_sync(0xffffffffu, send, msk);
                nv[r]     = keep + recv;          // sums -> regs 0..3
                nv[r + 4] = (keep - recv) * sgn;  // a-b  -> regs 4..7
            }
            #pragma unroll
            for (int r = 0; r < 8; r++) v[r] = nv[r];
        }

        // permuted bias/alpha: regs 0..3 <-> [pbase..pbase+3], 4..7 <-> [pbase+128..]
        const float* bp = bs + st * PDIM + pbase;
        const float* ap = alpha + st * PDIM + pbase;
        float4 b0 = *(const float4*)bp;
        float4 b1 = *(const float4*)(bp + 128);
        float4 a0 = *(const float4*)ap;
        float4 a1 = *(const float4*)(ap + 128);
        float bb[8] = {b0.x, b0.y, b0.z, b0.w, b1.x, b1.y, b1.z, b1.w};
        float aa[8] = {a0.x, a0.y, a0.z, a0.w, a1.x, a1.y, a1.z, a1.w};
        #pragma unroll
        for (int j = 0; j < 8; j++)
            sum += __cosf(v[j] + bb[j]) * aa[j];
    }

    #pragma unroll
    for (int off = 16; off; off >>= 1)
        sum += __shfl_down_sync(0xffffffffu, sum, off);
    if (lane == 0) g_partial[task] = sum;
}

// out[m] = FEAT_NORM * sum over 256 contiguous partials
__global__ void k_reduce(float* __restrict__ out) {
    int m = blockIdx.x;
    int t = threadIdx.x;   // 256 threads
    float v = g_partial[m * 256 + t];
    #pragma unroll
    for (int off = 16; off; off >>= 1)
        v += __shfl_down_sync(0xffffffffu, v, off);
    __shared__ float sm8[8];
    if ((t & 31) == 0) sm8[t >> 5] = v;
    __syncthreads();
    if (t < 8) {
        float w = sm8[t];
        #pragma unroll
        for (int off = 4; off; off >>= 1)
            w += __shfl_down_sync(0xffu, w, off);
        if (t == 0) out[m] = 0.015625f * w;   // FEAT_NORM = 1/64
    }
}

extern "C" void kernel_launch(void* const* d_in, const int* in_sizes, int n_in,
                              void* d_out, int out_size) {
    const float* rep       = (const float*)d_in[0];
    const int*   charges   = (const int*)d_in[1];
    const float* reductors = (const float*)d_in[2];
    const float* Dmat      = (const float*)d_in[3];
    const float* bias      = (const float*)d_in[4];
    const float* alpha     = (const float*)d_in[5];
    float* out = (float*)d_out;

    k_classify<<<1, 1024>>>(charges);
    dim3 gg(4 * KSPLIT, NROWS / BM, NS);   // (16, 32, 4); empty row-blocks exit early
    k_gemm<<<gg, 256>>>(rep, reductors);
    k_feat<<<NROWS * 4 / 8, 256>>>(charges, Dmat, bias, alpha);   // 1024 blocks
    k_reduce<<<MROWS, 256>>>(out);
}